// round 16
// baseline (speedup 1.0000x reference)
#include <cuda_runtime.h>
#include <cuda_fp16.h>
#include <math.h>
#include <stdint.h>

// Problem constants
#define B_  4
#define T_  2048
#define C_  1024
#define L_  256
#define H_  16
#define HS_ 64
#define BT_ (B_ * T_)   // 8192

// Scratch (allocation-free rule: __device__ globals)
__device__ __half    g_qh[BT_ * C_];
__device__ uint32_t  g_kf[(size_t)B_ * H_ * 32 * 4 * 2 * 256];  // K fragments, 16 MB
__device__ uint32_t  g_vf[(size_t)B_ * H_ * 32 * 4 * 2 * 256];  // V fragments, 16 MB
__device__ float     g_lat[BT_ * L_];
__device__ float     g_y[BT_ * C_];

__device__ __forceinline__ uint32_t f2tf(float f) {
    uint32_t u;
    asm("cvt.rna.tf32.f32 %0, %1;" : "=r"(u) : "f"(f));
    return u;
}
__device__ __forceinline__ float ex2(float x) {
    float r;
    asm("ex2.approx.f32 %0, %1;" : "=f"(r) : "f"(x));
    return r;
}
__device__ __forceinline__ uint32_t packh2(float a, float b) {
    __half2 h = __floats2half2_rn(a, b);
    return *(uint32_t*)&h;
}

#define MMA_TF32(d, a, b)                                                     \
    asm volatile(                                                             \
        "mma.sync.aligned.m16n8k8.row.col.f32.tf32.tf32.f32 "                 \
        "{%0,%1,%2,%3}, {%4,%5,%6,%7}, {%8,%9}, {%0,%1,%2,%3};"               \
        : "+f"((d)[0]), "+f"((d)[1]), "+f"((d)[2]), "+f"((d)[3])              \
        : "r"((a)[0]), "r"((a)[1]), "r"((a)[2]), "r"((a)[3]),                 \
          "r"((b)[0]), "r"((b)[1]))

#define MMA_F16(d, a0, a1, a2, a3, b0, b1)                                    \
    asm volatile(                                                             \
        "mma.sync.aligned.m16n8k16.row.col.f32.f16.f16.f32 "                  \
        "{%0,%1,%2,%3}, {%4,%5,%6,%7}, {%8,%9}, {%0,%1,%2,%3};"               \
        : "+f"((d)[0]), "+f"((d)[1]), "+f"((d)[2]), "+f"((d)[3])              \
        : "r"(a0), "r"(a1), "r"(a2), "r"(a3), "r"(b0), "r"(b1))

// ---------------------------------------------------------------------------
// TF32 tensor-core GEMM.
// mode 0: float out. mode 1: half row-major out (scaled).
// mode 3: K written as pre-tiled MMA B-fragments (see attn_frag).
// mode 4: V written as pre-tiled MMA B-fragments (key pairs via shfl).
// Fragment layout: idx = ((((b*16+h)*32 + kt)*4 + kkj)*2 + idx2)*256
//                        + nt*32 + g*4 + c,   one uint32 (= __half2) per lane.
// K frags: pair = consecutive DIMS (kk chunk), nt = key octet, g = key%8.
// V frags: pair = consecutive KEYS (j chunk),  nt = dim octet, g = dim%8.
// ---------------------------------------------------------------------------
#define APAD 20
#define BPAD 136

__global__ __launch_bounds__(256, 2)
void gemm_tf32(const float* __restrict__ A, const float* __restrict__ Bg,
               float* __restrict__ Cf, __half* __restrict__ Ch,
               uint32_t* __restrict__ Cu,
               int M, int N, int K, float oscale, int mode) {
    __shared__ uint32_t As[128 * APAD];
    __shared__ uint32_t Bs[16 * BPAD];

    const int tid = threadIdx.x;
    const int m0 = blockIdx.y * 128;
    const int n0 = blockIdx.x * 128;

    const int warp = tid >> 5;
    const int lane = tid & 31;
    const int wm = (warp & 1) * 64;
    const int wn = (warp >> 1) * 32;
    const int g = lane >> 2;
    const int c = lane & 3;

    const int arow = tid >> 1;
    const int ak   = (tid & 1) * 8;
    const int bkr  = tid >> 4;
    const int bcl  = (tid & 15) * 8;

    const float* Aptr = A + (size_t)(m0 + arow) * K + ak;
    const float* Bptr = Bg + (size_t)bkr * N + n0 + bcl;

    float4 pa0 = *(const float4*)(Aptr);
    float4 pa1 = *(const float4*)(Aptr + 4);
    float4 pb0 = *(const float4*)(Bptr);
    float4 pb1 = *(const float4*)(Bptr + 4);

    float acc[4][4][4];
    #pragma unroll
    for (int i = 0; i < 4; i++)
        #pragma unroll
        for (int j = 0; j < 4; j++)
            #pragma unroll
            for (int r = 0; r < 4; r++) acc[i][j][r] = 0.f;

    for (int kt = 0; kt < K; kt += 16) {
        {
            uint32_t* as = &As[arow * APAD + ak];
            as[0] = f2tf(pa0.x); as[1] = f2tf(pa0.y);
            as[2] = f2tf(pa0.z); as[3] = f2tf(pa0.w);
            as[4] = f2tf(pa1.x); as[5] = f2tf(pa1.y);
            as[6] = f2tf(pa1.z); as[7] = f2tf(pa1.w);
            uint32_t* bs = &Bs[bkr * BPAD + bcl];
            bs[0] = f2tf(pb0.x); bs[1] = f2tf(pb0.y);
            bs[2] = f2tf(pb0.z); bs[3] = f2tf(pb0.w);
            bs[4] = f2tf(pb1.x); bs[5] = f2tf(pb1.y);
            bs[6] = f2tf(pb1.z); bs[7] = f2tf(pb1.w);
        }
        __syncthreads();

        if (kt + 16 < K) {
            pa0 = *(const float4*)(Aptr + kt + 16);
            pa1 = *(const float4*)(Aptr + kt + 20);
            const float* bp = Bptr + (size_t)(kt + 16) * N;
            pb0 = *(const float4*)(bp);
            pb1 = *(const float4*)(bp + 4);
        }

        #pragma unroll
        for (int s = 0; s < 2; s++) {
            const int kk = s * 8;
            uint32_t af[4][4];
            uint32_t bf[4][2];
            #pragma unroll
            for (int mt = 0; mt < 4; mt++) {
                const int r0 = wm + mt * 16 + g;
                af[mt][0] = As[r0 * APAD + kk + c];
                af[mt][1] = As[(r0 + 8) * APAD + kk + c];
                af[mt][2] = As[r0 * APAD + kk + c + 4];
                af[mt][3] = As[(r0 + 8) * APAD + kk + c + 4];
            }
            #pragma unroll
            for (int nt = 0; nt < 4; nt++) {
                const int cc = wn + nt * 8 + g;
                bf[nt][0] = Bs[(kk + c) * BPAD + cc];
                bf[nt][1] = Bs[(kk + c + 4) * BPAD + cc];
            }
            #pragma unroll
            for (int mt = 0; mt < 4; mt++)
                #pragma unroll
                for (int nt = 0; nt < 4; nt++)
                    MMA_TF32(acc[mt][nt], af[mt], bf[nt]);
        }
        __syncthreads();
    }

    #pragma unroll
    for (int mt = 0; mt < 4; mt++) {
        const int row = m0 + wm + mt * 16 + g;
        #pragma unroll
        for (int nt = 0; nt < 4; nt++) {
            const int col = n0 + wn + nt * 8 + c * 2;
            float v0 = acc[mt][nt][0] * oscale;
            float v1 = acc[mt][nt][1] * oscale;
            float v2 = acc[mt][nt][2] * oscale;
            float v3 = acc[mt][nt][3] * oscale;
            if (mode == 0) {
                *(float2*)&Cf[(size_t)row * N + col] = make_float2(v0, v1);
                *(float2*)&Cf[(size_t)(row + 8) * N + col] = make_float2(v2, v3);
            } else if (mode == 1) {
                *(__half2*)&Ch[(size_t)row * N + col] = __floats2half2_rn(v0, v1);
                *(__half2*)&Ch[(size_t)(row + 8) * N + col] = __floats2half2_rn(v2, v3);
            } else if (mode == 3) {
                // K fragment store: pair = dims (col, col+1)
                const int hh = col >> 6, d = col & 63;
                const int kk = d >> 4, dd = d & 15;
                const int idx2 = dd >> 3, ccf = (dd & 7) >> 1;
                const int bb = row >> 11, t = row & 2047;
                const int ktt = t >> 6, ntk = (t & 63) >> 3, gk = t & 7;
                const size_t base =
                    ((((size_t)(bb * 16 + hh) * 32 + ktt) * 4 + kk) * 2 + idx2) * 256
                    + gk * 4 + ccf;
                Cu[base + ntk * 32]       = packh2(v0, v1);
                Cu[base + (ntk + 1) * 32] = packh2(v2, v3);   // row+8 -> next key octet
            } else {
                // mode 4: V fragment store: pair = keys (row, row+1) via shfl
                float p0 = __shfl_down_sync(0xffffffffu, v0, 4);
                float p1 = __shfl_down_sync(0xffffffffu, v1, 4);
                float p2 = __shfl_down_sync(0xffffffffu, v2, 4);
                float p3 = __shfl_down_sync(0xffffffffu, v3, 4);
                if (!(g & 1)) {
                    const int hh = col >> 6, d = col & 63;
                    const int ntp = d >> 3, gd = d & 7;      // gd even (col even)
                    const int bb = row >> 11, t = row & 2047;
                    const int ktt = t >> 6, jj = (t & 63) >> 4;
                    const int cv = (t & 15) >> 1;            // = g>>1, 0..3
                    const size_t base =
                        ((((size_t)(bb * 16 + hh) * 32 + ktt) * 4 + jj) * 2) * 256 + cv;
                    Cu[base + ntp * 32 + gd * 4]             = packh2(v0, p0);
                    Cu[base + ntp * 32 + (gd + 1) * 4]       = packh2(v1, p1);
                    Cu[base + 256 + ntp * 32 + gd * 4]       = packh2(v2, p2);  // keys +8
                    Cu[base + 256 + ntp * 32 + (gd + 1) * 4] = packh2(v3, p3);
                }
            }
        }
    }
}

// ---------------------------------------------------------------------------
// Barrier-free FP16 causal flash attention.
// 128-query tile, 128 threads (4 warps), warp = 32 rows (2 m-tiles).
// K and V arrive pre-tiled in MMA fragment layout -> every operand fetched
// with a fully-coalesced 128B warp LDG. NO smem, NO cp.async, NO barriers:
// warps free-run their own key ranges; 12 warps/SM interleave phases.
// softmax p = exp2(min(s,14)), per-lane row sums, reduced once at end.
// ---------------------------------------------------------------------------
__global__ __launch_bounds__(128, 3)
void attn_frag(const __half* __restrict__ qh, const uint32_t* __restrict__ kf,
               const uint32_t* __restrict__ vf, float* __restrict__ y) {
    const int tid  = threadIdx.x;
    const int warp = tid >> 5;
    const int lane = tid & 31;
    const int g = lane >> 2;
    const int c = lane & 3;

    const int bh = blockIdx.x;
    const int b = bh >> 4;
    const int h = bh & 15;
    const int qt = (int)gridDim.y - 1 - (int)blockIdx.y;   // heavy first

    const int wm = warp * 32;
    const int wfirst = qt * 128 + wm;
    const int row0g = wfirst + g;
    const int row1g = row0g + 8;
    const int row2g = row0g + 16;
    const int row3g = row0g + 24;

    // ---- Q fragments in registers ----
    uint32_t qf[4][8];
    {
        const __half* q0 = qh + (size_t)(b * T_ + row0g) * C_ + h * HS_;
        const __half* q1 = qh + (size_t)(b * T_ + row1g) * C_ + h * HS_;
        const __half* q2 = qh + (size_t)(b * T_ + row2g) * C_ + h * HS_;
        const __half* q3 = qh + (size_t)(b * T_ + row3g) * C_ + h * HS_;
        #pragma unroll
        for (int kk = 0; kk < 4; kk++) {
            qf[kk][0] = *(const uint32_t*)(q0 + kk * 16 + 2 * c);
            qf[kk][1] = *(const uint32_t*)(q1 + kk * 16 + 2 * c);
            qf[kk][2] = *(const uint32_t*)(q0 + kk * 16 + 2 * c + 8);
            qf[kk][3] = *(const uint32_t*)(q1 + kk * 16 + 2 * c + 8);
            qf[kk][4] = *(const uint32_t*)(q2 + kk * 16 + 2 * c);
            qf[kk][5] = *(const uint32_t*)(q3 + kk * 16 + 2 * c);
            qf[kk][6] = *(const uint32_t*)(q2 + kk * 16 + 2 * c + 8);
            qf[kk][7] = *(const uint32_t*)(q3 + kk * 16 + 2 * c + 8);
        }
    }

    const uint32_t* kfb = kf + (size_t)bh * 32 * 2048;
    const uint32_t* vfb = vf + (size_t)bh * 32 * 2048;

    float o0[8][4], o1[8][4];
    #pragma unroll
    for (int nt = 0; nt < 8; nt++)
        #pragma unroll
        for (int r = 0; r < 4; r++) { o0[nt][r] = 0.f; o1[nt][r] = 0.f; }
    float l0 = 0.f, l1 = 0.f, l2 = 0.f, l3 = 0.f;

    const int ktw = (wfirst + 31) >> 6;   // warp's last useful 64-key tile

    for (int kt = 0; kt <= ktw; kt++) {
        const int kstart = kt * 64;
        const uint32_t* kkb = kfb + kt * 2048 + lane;

        // ---- S = Q K^T: coalesced fragment LDGs + MMAs ----
        float s0[8][4], s1[8][4];
        #pragma unroll
        for (int nt = 0; nt < 8; nt++)
            #pragma unroll
            for (int r = 0; r < 4; r++) { s0[nt][r] = 0.f; s1[nt][r] = 0.f; }

        #pragma unroll
        for (int kk = 0; kk < 4; kk++) {
            const uint32_t* p = kkb + kk * 512;
            uint32_t bf[16];
            #pragma unroll
            for (int nt = 0; nt < 8; nt++) {
                bf[2 * nt]     = p[nt * 32];
                bf[2 * nt + 1] = p[256 + nt * 32];
            }
            #pragma unroll
            for (int nt = 0; nt < 8; nt++) {
                MMA_F16(s0[nt], qf[kk][0], qf[kk][1], qf[kk][2], qf[kk][3],
                        bf[2 * nt], bf[2 * nt + 1]);
                MMA_F16(s1[nt], qf[kk][4], qf[kk][5], qf[kk][6], qf[kk][7],
                        bf[2 * nt], bf[2 * nt + 1]);
            }
        }

        // ---- causal mask (tiles crossing the diagonal) ----
        if (kstart + 63 > wfirst) {
            #pragma unroll
            for (int nt = 0; nt < 8; nt++) {
                const int col = kstart + nt * 8 + 2 * c;
                if (col     > row0g) s0[nt][0] = -1e4f;
                if (col + 1 > row0g) s0[nt][1] = -1e4f;
                if (col     > row1g) s0[nt][2] = -1e4f;
                if (col + 1 > row1g) s0[nt][3] = -1e4f;
                if (col     > row2g) s1[nt][0] = -1e4f;
                if (col + 1 > row2g) s1[nt][1] = -1e4f;
                if (col     > row3g) s1[nt][2] = -1e4f;
                if (col + 1 > row3g) s1[nt][3] = -1e4f;
            }
        }

        // ---- p = exp2(min(s,14)); per-lane row sums ----
        #pragma unroll
        for (int nt = 0; nt < 8; nt++) {
            s0[nt][0] = ex2(fminf(s0[nt][0], 14.f));
            s0[nt][1] = ex2(fminf(s0[nt][1], 14.f));
            s0[nt][2] = ex2(fminf(s0[nt][2], 14.f));
            s0[nt][3] = ex2(fminf(s0[nt][3], 14.f));
            l0 += s0[nt][0] + s0[nt][1];
            l1 += s0[nt][2] + s0[nt][3];
            s1[nt][0] = ex2(fminf(s1[nt][0], 14.f));
            s1[nt][1] = ex2(fminf(s1[nt][1], 14.f));
            s1[nt][2] = ex2(fminf(s1[nt][2], 14.f));
            s1[nt][3] = ex2(fminf(s1[nt][3], 14.f));
            l2 += s1[nt][0] + s1[nt][1];
            l3 += s1[nt][2] + s1[nt][3];
        }

        // ---- O += P V: coalesced V-fragment LDGs + MMAs ----
        const uint32_t* vjb = vfb + kt * 2048 + lane;
        #pragma unroll
        for (int j = 0; j < 4; j++) {
            const uint32_t a00 = packh2(s0[2 * j][0],     s0[2 * j][1]);
            const uint32_t a01 = packh2(s0[2 * j][2],     s0[2 * j][3]);
            const uint32_t a02 = packh2(s0[2 * j + 1][0], s0[2 * j + 1][1]);
            const uint32_t a03 = packh2(s0[2 * j + 1][2], s0[2 * j + 1][3]);
            const uint32_t a10 = packh2(s1[2 * j][0],     s1[2 * j][1]);
            const uint32_t a11 = packh2(s1[2 * j][2],     s1[2 * j][3]);
            const uint32_t a12 = packh2(s1[2 * j + 1][0], s1[2 * j + 1][1]);
            const uint32_t a13 = packh2(s1[2 * j + 1][2], s1[2 * j + 1][3]);
            const uint32_t* p = vjb + j * 512;
            uint32_t vb[16];
            #pragma unroll
            for (int ntp = 0; ntp < 8; ntp++) {
                vb[2 * ntp]     = p[ntp * 32];
                vb[2 * ntp + 1] = p[256 + ntp * 32];
            }
            #pragma unroll
            for (int ntp = 0; ntp < 8; ntp++) {
                MMA_F16(o0[ntp], a00, a01, a02, a03, vb[2 * ntp], vb[2 * ntp + 1]);
                MMA_F16(o1[ntp], a10, a11, a12, a13, vb[2 * ntp], vb[2 * ntp + 1]);
            }
        }
    }

    // ---- reduce row sums across the 4 c-lanes (once) ----
    l0 += __shfl_xor_sync(0xffffffffu, l0, 1);
    l0 += __shfl_xor_sync(0xffffffffu, l0, 2);
    l1 += __shfl_xor_sync(0xffffffffu, l1, 1);
    l1 += __shfl_xor_sync(0xffffffffu, l1, 2);
    l2 += __shfl_xor_sync(0xffffffffu, l2, 1);
    l2 += __shfl_xor_sync(0xffffffffu, l2, 2);
    l3 += __shfl_xor_sync(0xffffffffu, l3, 1);
    l3 += __shfl_xor_sync(0xffffffffu, l3, 2);

    const float inv0 = 1.f / l0;
    const float inv1 = 1.f / l1;
    const float inv2 = 1.f / l2;
    const float inv3 = 1.f / l3;
    float* dst0 = y + (size_t)(b * T_ + row0g) * C_ + h * HS_;
    float* dst1 = y + (size_t)(b * T_ + row1g) * C_ + h * HS_;
    float* dst2 = y + (size_t)(b * T_ + row2g) * C_ + h * HS_;
    float* dst3 = y + (size_t)(b * T_ + row3g) * C_ + h * HS_;
    #pragma unroll
    for (int nt = 0; nt < 8; nt++) {
        const int col = nt * 8 + 2 * c;
        *(float2*)(dst0 + col) = make_float2(o0[nt][0] * inv0, o0[nt][1] * inv0);
        *(float2*)(dst1 + col) = make_float2(o0[nt][2] * inv1, o0[nt][3] * inv1);
        *(float2*)(dst2 + col) = make_float2(o1[nt][0] * inv2, o1[nt][1] * inv2);
        *(float2*)(dst3 + col) = make_float2(o1[nt][2] * inv3, o1[nt][3] * inv3);
    }
}

// ---------------------------------------------------------------------------
extern "C" void kernel_launch(void* const* d_in, const int* in_sizes, int n_in,
                              void* d_out, int out_size) {
    const float* x     = (const float*)d_in[0];
    const float* Wq    = (const float*)d_in[1];
    const float* Wkvd  = (const float*)d_in[2];
    const float* Wku   = (const float*)d_in[3];
    const float* Wvu   = (const float*)d_in[4];
    const float* Wout  = (const float*)d_in[5];
    float* out = (float*)d_out;

    __half* qh;
    uint32_t *kfp, *vfp;
    float *lat, *y;
    cudaGetSymbolAddress((void**)&qh,  g_qh);
    cudaGetSymbolAddress((void**)&kfp, g_kf);
    cudaGetSymbolAddress((void**)&vfp, g_vf);
    cudaGetSymbolAddress((void**)&lat, g_lat);
    cudaGetSymbolAddress((void**)&y,   g_y);

    dim3 blk(256);

    // q = (0.125*log2e) * (x @ Wq) -> fp16 row-major
    gemm_tf32<<<dim3(C_ / 128, BT_ / 128), blk>>>(x, Wq, nullptr, qh, nullptr,
                                                  BT_, C_, C_, 0.18033688f, 1);
    // latent = x @ W_kv_down -> f32
    gemm_tf32<<<dim3(L_ / 128, BT_ / 128), blk>>>(x, Wkvd, lat, nullptr, nullptr,
                                                  BT_, L_, C_, 1.f, 0);
    // k = latent @ W_k_up -> pre-tiled K fragments
    gemm_tf32<<<dim3(C_ / 128, BT_ / 128), blk>>>(lat, Wku, nullptr, nullptr, kfp,
                                                  BT_, C_, L_, 1.f, 3);
    // v = latent @ W_v_up -> pre-tiled V fragments
    gemm_tf32<<<dim3(C_ / 128, BT_ / 128), blk>>>(lat, Wvu, nullptr, nullptr, vfp,
                                                  BT_, C_, L_, 1.f, 4);

    // barrier-free fused causal attention -> y
    attn_frag<<<dim3(B_ * H_, T_ / 128), 128>>>(qh, kfp, vfp, y);

    // out = y @ W_out -> f32
    gemm_tf32<<<dim3(C_ / 128, BT_ / 128), blk>>>(y, Wout, out, nullptr, nullptr,
                                                  BT_, C_, C_, 1.f, 0);
}

// round 17
// speedup vs baseline: 1.1286x; 1.1286x over previous
#include <cuda_runtime.h>
#include <cuda_fp16.h>
#include <math.h>
#include <stdint.h>

// Problem constants
#define B_  4
#define T_  2048
#define C_  1024
#define L_  256
#define H_  16
#define HS_ 64
#define BT_ (B_ * T_)   // 8192

// Scratch (allocation-free rule: __device__ globals)
__device__ __half g_qh[BT_ * C_];
__device__ __half g_kh[BT_ * C_];
__device__ __half g_vh[BT_ * C_];
__device__ float  g_lat[BT_ * L_];
__device__ float  g_y[BT_ * C_];

__device__ __forceinline__ uint32_t f2tf(float f) {
    uint32_t u;
    asm("cvt.rna.tf32.f32 %0, %1;" : "=r"(u) : "f"(f));
    return u;
}
__device__ __forceinline__ uint32_t packh2(float a, float b) {
    __half2 h = __floats2half2_rn(a, b);
    return *(uint32_t*)&h;
}
__device__ __forceinline__ uint32_t hmin2(uint32_t a, uint32_t b) {
    uint32_t r;
    asm("min.f16x2 %0, %1, %2;" : "=r"(r) : "r"(a), "r"(b));
    return r;
}
__device__ __forceinline__ uint32_t h2ex2(uint32_t a) {
    uint32_t r;
    asm("ex2.approx.f16x2 %0, %1;" : "=r"(r) : "r"(a));
    return r;
}
__device__ __forceinline__ void cp_async16(uint32_t dst, const void* src) {
    asm volatile("cp.async.cg.shared.global [%0], [%1], 16;" :: "r"(dst), "l"(src));
}
#define CP_COMMIT() asm volatile("cp.async.commit_group;")
#define CP_WAIT0()  asm volatile("cp.async.wait_group 0;" ::: "memory")

#define MMA_TF32(d, a, b)                                                     \
    asm volatile(                                                             \
        "mma.sync.aligned.m16n8k8.row.col.f32.tf32.tf32.f32 "                 \
        "{%0,%1,%2,%3}, {%4,%5,%6,%7}, {%8,%9}, {%0,%1,%2,%3};"               \
        : "+f"((d)[0]), "+f"((d)[1]), "+f"((d)[2]), "+f"((d)[3])              \
        : "r"((a)[0]), "r"((a)[1]), "r"((a)[2]), "r"((a)[3]),                 \
          "r"((b)[0]), "r"((b)[1]))

#define MMA_F16(d, a0, a1, a2, a3, b0, b1)                                    \
    asm volatile(                                                             \
        "mma.sync.aligned.m16n8k16.row.col.f32.f16.f16.f32 "                  \
        "{%0,%1,%2,%3}, {%4,%5,%6,%7}, {%8,%9}, {%0,%1,%2,%3};"               \
        : "+f"((d)[0]), "+f"((d)[1]), "+f"((d)[2]), "+f"((d)[3])              \
        : "r"(a0), "r"(a1), "r"(a2), "r"(a3), "r"(b0), "r"(b1))

#define LDSM4(r0, r1, r2, r3, addr)                                           \
    asm volatile("ldmatrix.sync.aligned.m8n8.x4.shared.b16 {%0,%1,%2,%3}, [%4];" \
        : "=r"(r0), "=r"(r1), "=r"(r2), "=r"(r3) : "r"(addr))

#define LDSM4T(r0, r1, r2, r3, addr)                                          \
    asm volatile("ldmatrix.sync.aligned.m8n8.x4.trans.shared.b16 {%0,%1,%2,%3}, [%4];" \
        : "=r"(r0), "=r"(r1), "=r"(r2), "=r"(r3) : "r"(addr))

#define HONES 0x3C003C00u     // (1.0h, 1.0h)
#define HCL14 0x4B004B00u     // (14.h, 14.h)

// ---------------------------------------------------------------------------
// TF32 tensor-core GEMM. mode 0: write float. mode 1: write __half (scaled).
// ---------------------------------------------------------------------------
#define APAD 20
#define BPAD 136

__global__ __launch_bounds__(256, 2)
void gemm_tf32(const float* __restrict__ A, const float* __restrict__ Bg,
               float* __restrict__ Cf, __half* __restrict__ Ch,
               int M, int N, int K, float oscale, int mode) {
    __shared__ uint32_t As[128 * APAD];
    __shared__ uint32_t Bs[16 * BPAD];

    const int tid = threadIdx.x;
    const int m0 = blockIdx.y * 128;
    const int n0 = blockIdx.x * 128;

    const int warp = tid >> 5;
    const int lane = tid & 31;
    const int wm = (warp & 1) * 64;
    const int wn = (warp >> 1) * 32;
    const int g = lane >> 2;
    const int c = lane & 3;

    const int arow = tid >> 1;
    const int ak   = (tid & 1) * 8;
    const int bkr  = tid >> 4;
    const int bcl  = (tid & 15) * 8;

    const float* Aptr = A + (size_t)(m0 + arow) * K + ak;
    const float* Bptr = Bg + (size_t)bkr * N + n0 + bcl;

    float4 pa0 = *(const float4*)(Aptr);
    float4 pa1 = *(const float4*)(Aptr + 4);
    float4 pb0 = *(const float4*)(Bptr);
    float4 pb1 = *(const float4*)(Bptr + 4);

    float acc[4][4][4];
    #pragma unroll
    for (int i = 0; i < 4; i++)
        #pragma unroll
        for (int j = 0; j < 4; j++)
            #pragma unroll
            for (int r = 0; r < 4; r++) acc[i][j][r] = 0.f;

    for (int kt = 0; kt < K; kt += 16) {
        {
            uint32_t* as = &As[arow * APAD + ak];
            as[0] = f2tf(pa0.x); as[1] = f2tf(pa0.y);
            as[2] = f2tf(pa0.z); as[3] = f2tf(pa0.w);
            as[4] = f2tf(pa1.x); as[5] = f2tf(pa1.y);
            as[6] = f2tf(pa1.z); as[7] = f2tf(pa1.w);
            uint32_t* bs = &Bs[bkr * BPAD + bcl];
            bs[0] = f2tf(pb0.x); bs[1] = f2tf(pb0.y);
            bs[2] = f2tf(pb0.z); bs[3] = f2tf(pb0.w);
            bs[4] = f2tf(pb1.x); bs[5] = f2tf(pb1.y);
            bs[6] = f2tf(pb1.z); bs[7] = f2tf(pb1.w);
        }
        __syncthreads();

        if (kt + 16 < K) {
            pa0 = *(const float4*)(Aptr + kt + 16);
            pa1 = *(const float4*)(Aptr + kt + 20);
            const float* bp = Bptr + (size_t)(kt + 16) * N;
            pb0 = *(const float4*)(bp);
            pb1 = *(const float4*)(bp + 4);
        }

        #pragma unroll
        for (int s = 0; s < 2; s++) {
            const int kk = s * 8;
            uint32_t af[4][4];
            uint32_t bf[4][2];
            #pragma unroll
            for (int mt = 0; mt < 4; mt++) {
                const int r0 = wm + mt * 16 + g;
                af[mt][0] = As[r0 * APAD + kk + c];
                af[mt][1] = As[(r0 + 8) * APAD + kk + c];
                af[mt][2] = As[r0 * APAD + kk + c + 4];
                af[mt][3] = As[(r0 + 8) * APAD + kk + c + 4];
            }
            #pragma unroll
            for (int nt = 0; nt < 4; nt++) {
                const int cc = wn + nt * 8 + g;
                bf[nt][0] = Bs[(kk + c) * BPAD + cc];
                bf[nt][1] = Bs[(kk + c + 4) * BPAD + cc];
            }
            #pragma unroll
            for (int mt = 0; mt < 4; mt++)
                #pragma unroll
                for (int nt = 0; nt < 4; nt++)
                    MMA_TF32(acc[mt][nt], af[mt], bf[nt]);
        }
        __syncthreads();
    }

    #pragma unroll
    for (int mt = 0; mt < 4; mt++) {
        const int row = m0 + wm + mt * 16 + g;
        #pragma unroll
        for (int nt = 0; nt < 4; nt++) {
            const int col = n0 + wn + nt * 8 + c * 2;
            float v0 = acc[mt][nt][0] * oscale;
            float v1 = acc[mt][nt][1] * oscale;
            float v2 = acc[mt][nt][2] * oscale;
            float v3 = acc[mt][nt][3] * oscale;
            if (mode == 0) {
                *(float2*)&Cf[(size_t)row * N + col] = make_float2(v0, v1);
                *(float2*)&Cf[(size_t)(row + 8) * N + col] = make_float2(v2, v3);
            } else {
                *(__half2*)&Ch[(size_t)row * N + col] = __floats2half2_rn(v0, v1);
                *(__half2*)&Ch[(size_t)(row + 8) * N + col] = __floats2half2_rn(v2, v3);
            }
        }
    }
}

// ---------------------------------------------------------------------------
// FP16 causal flash attention v9 (base: R15 v8 structure).
// MUFU relief: exp computed as ex2.approx.f16x2 on packed score pairs
// (half the MUFU ops); row sums computed ON THE TENSOR PIPE via an extra
// MMA against an all-ones B fragment (exact fp32, sums over ALL lanes ->
// no FADD chain, no final shfl reduce).
// 256-query tile, warp = 32 rows (2 m-tiles), 64-key tiles, 2-stage
// cp.async, 1 CTA/SM.
// ---------------------------------------------------------------------------
#define QTILE 256
#define KROWB 144
#define TILEB (64 * KROWB)
#define ATTN_SMEM (4 * TILEB)     // 36864 B

__global__ __launch_bounds__(256, 1)
void attn_f16x(const __half* __restrict__ qh, const __half* __restrict__ kh,
               const __half* __restrict__ vh, float* __restrict__ y) {
    extern __shared__ char smc[];
    const uint32_t sb = (uint32_t)__cvta_generic_to_shared(smc);
    const uint32_t kbuf[2] = { sb, sb + TILEB };
    const uint32_t vbuf[2] = { sb + 2 * TILEB, sb + 3 * TILEB };

    const int tid  = threadIdx.x;
    const int warp = tid >> 5;
    const int lane = tid & 31;
    const int g = lane >> 2;
    const int c = lane & 3;

    const int bh = blockIdx.x;
    const int b = bh >> 4;
    const int h = bh & 15;
    const int qt = (int)gridDim.y - 1 - (int)blockIdx.y;   // heavy first

    const int wm = warp * 32;
    const int wfirst = qt * QTILE + wm;
    const int row0g = wfirst + g;
    const int row1g = row0g + 8;
    const int row2g = row0g + 16;
    const int row3g = row0g + 24;

    // ---- Q fragments in registers ----
    uint32_t qf[4][8];
    {
        const __half* q0 = qh + (size_t)(b * T_ + row0g) * C_ + h * HS_;
        const __half* q1 = qh + (size_t)(b * T_ + row1g) * C_ + h * HS_;
        const __half* q2 = qh + (size_t)(b * T_ + row2g) * C_ + h * HS_;
        const __half* q3 = qh + (size_t)(b * T_ + row3g) * C_ + h * HS_;
        #pragma unroll
        for (int kk = 0; kk < 4; kk++) {
            qf[kk][0] = *(const uint32_t*)(q0 + kk * 16 + 2 * c);
            qf[kk][1] = *(const uint32_t*)(q1 + kk * 16 + 2 * c);
            qf[kk][2] = *(const uint32_t*)(q0 + kk * 16 + 2 * c + 8);
            qf[kk][3] = *(const uint32_t*)(q1 + kk * 16 + 2 * c + 8);
            qf[kk][4] = *(const uint32_t*)(q2 + kk * 16 + 2 * c);
            qf[kk][5] = *(const uint32_t*)(q3 + kk * 16 + 2 * c);
            qf[kk][6] = *(const uint32_t*)(q2 + kk * 16 + 2 * c + 8);
            qf[kk][7] = *(const uint32_t*)(q3 + kk * 16 + 2 * c + 8);
        }
    }

    // ---- K/V loader ----
    const int lrow = tid >> 2;
    const int lcol = (tid & 3) * 16;
    const __half* kg = kh + (size_t)(b * T_ + lrow) * C_ + h * HS_ + lcol;
    const __half* vg = vh + (size_t)(b * T_ + lrow) * C_ + h * HS_ + lcol;
    const size_t tstep = (size_t)64 * C_;
    const uint32_t dst_off = (uint32_t)(lrow * KROWB + lcol * 2);

    const int ktmax  = 4 * qt + 3;
    const int ktwmax = (wfirst + 31) >> 6;

    cp_async16(kbuf[0] + dst_off,      kg);
    cp_async16(kbuf[0] + dst_off + 16, kg + 8);
    cp_async16(vbuf[0] + dst_off,      vg);
    cp_async16(vbuf[0] + dst_off + 16, vg + 8);
    CP_COMMIT();

    float o0[8][4], o1[8][4];
    float lo0[4], lo1[4];         // tensor-pipe row-sum accumulators
    #pragma unroll
    for (int nt = 0; nt < 8; nt++)
        #pragma unroll
        for (int r = 0; r < 4; r++) { o0[nt][r] = 0.f; o1[nt][r] = 0.f; }
    #pragma unroll
    for (int r = 0; r < 4; r++) { lo0[r] = 0.f; lo1[r] = 0.f; }

    const int lm = lane >> 3;
    const int lr = lane & 7;

    for (int kt = 0; kt <= ktmax; kt++) {
        CP_WAIT0();
        __syncthreads();

        if (kt < ktmax) {
            const int nb = (kt + 1) & 1;
            const __half* ks = kg + (size_t)(kt + 1) * tstep;
            const __half* vs = vg + (size_t)(kt + 1) * tstep;
            cp_async16(kbuf[nb] + dst_off,      ks);
            cp_async16(kbuf[nb] + dst_off + 16, ks + 8);
            cp_async16(vbuf[nb] + dst_off,      vs);
            cp_async16(vbuf[nb] + dst_off + 16, vs + 8);
            CP_COMMIT();
        }

        if (kt > ktwmax) continue;

        const uint32_t ks = kbuf[kt & 1];
        const uint32_t vs = vbuf[kt & 1];
        const int kstart = kt * 64;

        // ---- S = Q K^T for both m-tiles; shared K fragments ----
        float s0[8][4], s1[8][4];
        #pragma unroll
        for (int nt = 0; nt < 8; nt++)
            #pragma unroll
            for (int r = 0; r < 4; r++) { s0[nt][r] = 0.f; s1[nt][r] = 0.f; }

        #pragma unroll
        for (int kk = 0; kk < 4; kk++) {
            #pragma unroll
            for (int ntp = 0; ntp < 4; ntp++) {
                const uint32_t addr = ks
                    + (uint32_t)((ntp * 16 + (lm >> 1) * 8 + lr) * KROWB)
                    + (uint32_t)((kk * 16 + (lm & 1) * 8) * 2);
                uint32_t r0, r1, r2, r3;
                LDSM4(r0, r1, r2, r3, addr);
                MMA_F16(s0[2 * ntp],     qf[kk][0], qf[kk][1], qf[kk][2], qf[kk][3], r0, r1);
                MMA_F16(s0[2 * ntp + 1], qf[kk][0], qf[kk][1], qf[kk][2], qf[kk][3], r2, r3);
                MMA_F16(s1[2 * ntp],     qf[kk][4], qf[kk][5], qf[kk][6], qf[kk][7], r0, r1);
                MMA_F16(s1[2 * ntp + 1], qf[kk][4], qf[kk][5], qf[kk][6], qf[kk][7], r2, r3);
            }
        }

        // ---- causal mask (only tiles crossing the diagonal) ----
        if (kstart + 63 > wfirst) {
            #pragma unroll
            for (int nt = 0; nt < 8; nt++) {
                const int col = kstart + nt * 8 + 2 * c;
                if (col     > row0g) s0[nt][0] = -1e4f;
                if (col + 1 > row0g) s0[nt][1] = -1e4f;
                if (col     > row1g) s0[nt][2] = -1e4f;
                if (col + 1 > row1g) s0[nt][3] = -1e4f;
                if (col     > row2g) s1[nt][0] = -1e4f;
                if (col + 1 > row2g) s1[nt][1] = -1e4f;
                if (col     > row3g) s1[nt][2] = -1e4f;
                if (col + 1 > row3g) s1[nt][3] = -1e4f;
            }
        }

        // ---- pack -> clamp -> exp2 (f16x2 MUFU): 2 scores per op ----
        uint32_t pu0[16], pu1[16];
        #pragma unroll
        for (int nt = 0; nt < 8; nt++) {
            pu0[2 * nt]     = h2ex2(hmin2(packh2(s0[nt][0], s0[nt][1]), HCL14));
            pu0[2 * nt + 1] = h2ex2(hmin2(packh2(s0[nt][2], s0[nt][3]), HCL14));
            pu1[2 * nt]     = h2ex2(hmin2(packh2(s1[nt][0], s1[nt][1]), HCL14));
            pu1[2 * nt + 1] = h2ex2(hmin2(packh2(s1[nt][2], s1[nt][3]), HCL14));
        }

        // ---- O += P V ; row sums via ones-MMA on the tensor pipe ----
        #pragma unroll
        for (int j = 0; j < 4; j++) {
            const uint32_t a00 = pu0[4 * j],     a01 = pu0[4 * j + 1];
            const uint32_t a02 = pu0[4 * j + 2], a03 = pu0[4 * j + 3];
            const uint32_t a10 = pu1[4 * j],     a11 = pu1[4 * j + 1];
            const uint32_t a12 = pu1[4 * j + 2], a13 = pu1[4 * j + 3];
            MMA_F16(lo0, a00, a01, a02, a03, HONES, HONES);
            MMA_F16(lo1, a10, a11, a12, a13, HONES, HONES);
            #pragma unroll
            for (int ntp = 0; ntp < 4; ntp++) {
                const uint32_t addr = vs
                    + (uint32_t)((j * 16 + (lm & 1) * 8 + lr) * KROWB)
                    + (uint32_t)((ntp * 16 + (lm >> 1) * 8) * 2);
                uint32_t r0, r1, r2, r3;
                LDSM4T(r0, r1, r2, r3, addr);
                MMA_F16(o0[2 * ntp],     a00, a01, a02, a03, r0, r1);
                MMA_F16(o0[2 * ntp + 1], a00, a01, a02, a03, r2, r3);
                MMA_F16(o1[2 * ntp],     a10, a11, a12, a13, r0, r1);
                MMA_F16(o1[2 * ntp + 1], a10, a11, a12, a13, r2, r3);
            }
        }
    }

    // ---- normalize and write (row sums already complete in lo*) ----
    const float inv0 = 1.f / lo0[0];
    const float inv1 = 1.f / lo0[2];
    const float inv2 = 1.f / lo1[0];
    const float inv3 = 1.f / lo1[2];
    float* dst0 = y + (size_t)(b * T_ + row0g) * C_ + h * HS_;
    float* dst1 = y + (size_t)(b * T_ + row1g) * C_ + h * HS_;
    float* dst2 = y + (size_t)(b * T_ + row2g) * C_ + h * HS_;
    float* dst3 = y + (size_t)(b * T_ + row3g) * C_ + h * HS_;
    #pragma unroll
    for (int nt = 0; nt < 8; nt++) {
        const int col = nt * 8 + 2 * c;
        *(float2*)(dst0 + col) = make_float2(o0[nt][0] * inv0, o0[nt][1] * inv0);
        *(float2*)(dst1 + col) = make_float2(o0[nt][2] * inv1, o0[nt][3] * inv1);
        *(float2*)(dst2 + col) = make_float2(o1[nt][0] * inv2, o1[nt][1] * inv2);
        *(float2*)(dst3 + col) = make_float2(o1[nt][2] * inv3, o1[nt][3] * inv3);
    }
}

// ---------------------------------------------------------------------------
extern "C" void kernel_launch(void* const* d_in, const int* in_sizes, int n_in,
                              void* d_out, int out_size) {
    const float* x     = (const float*)d_in[0];
    const float* Wq    = (const float*)d_in[1];
    const float* Wkvd  = (const float*)d_in[2];
    const float* Wku   = (const float*)d_in[3];
    const float* Wvu   = (const float*)d_in[4];
    const float* Wout  = (const float*)d_in[5];
    float* out = (float*)d_out;

    __half *qh, *kh, *vh;
    float *lat, *y;
    cudaGetSymbolAddress((void**)&qh,  g_qh);
    cudaGetSymbolAddress((void**)&kh,  g_kh);
    cudaGetSymbolAddress((void**)&vh,  g_vh);
    cudaGetSymbolAddress((void**)&lat, g_lat);
    cudaGetSymbolAddress((void**)&y,   g_y);

    cudaFuncSetAttribute(attn_f16x, cudaFuncAttributeMaxDynamicSharedMemorySize, ATTN_SMEM);

    dim3 blk(256);

    // q = (0.125*log2e) * (x @ Wq) -> fp16
    gemm_tf32<<<dim3(C_ / 128, BT_ / 128), blk>>>(x, Wq, nullptr, qh, BT_, C_, C_, 0.18033688f, 1);
    // latent = x @ W_kv_down -> f32
    gemm_tf32<<<dim3(L_ / 128, BT_ / 128), blk>>>(x, Wkvd, lat, nullptr, BT_, L_, C_, 1.f, 0);
    // k = latent @ W_k_up -> fp16
    gemm_tf32<<<dim3(C_ / 128, BT_ / 128), blk>>>(lat, Wku, nullptr, kh, BT_, C_, L_, 1.f, 1);
    // v = latent @ W_v_up -> fp16
    gemm_tf32<<<dim3(C_ / 128, BT_ / 128), blk>>>(lat, Wvu, nullptr, vh, BT_, C_, L_, 1.f, 1);

    // fused causal attention -> y
    attn_f16x<<<dim3(B_ * H_, T_ / QTILE), 256, ATTN_SMEM>>>(qh, kh, vh, y);

    // out = y @ W_out -> f32
    gemm_tf32<<<dim3(C_ / 128, BT_ / 128), blk>>>(y, Wout, out, nullptr, BT_, C_, C_, 1.f, 0);
}